// round 8
// baseline (speedup 1.0000x reference)
#include <cuda_runtime.h>
#include <cstdint>
#include <math_constants.h>

constexpr int C  = 128;
constexpr int KN = 16;
constexpr int NMAX = 100000;

// ---------------- device scratch -------------------------------------------
__device__ float g_h0[(size_t)NMAX * C];
__device__ float g_pooled[(size_t)NMAX * C];
__device__ float g_t[(size_t)NMAX * C];
__device__ float g_u[(size_t)NMAX * C];

__device__ float g_sum[4][C];
__device__ float g_sq[4][C];
__device__ float g_scale[4][C];
__device__ float g_shift[4][C];

// ---------------- helpers ----------------------------------------------------
__device__ __forceinline__ uint32_t f2tf32(float x) {
    uint32_t r;
    asm("cvt.rna.tf32.f32 %0, %1;" : "=r"(r) : "f"(x));
    return r;
}

__device__ __forceinline__ void mma_tf32(float* d, const uint32_t* a,
                                         uint32_t b0, uint32_t b1) {
    asm volatile(
        "mma.sync.aligned.m16n8k8.row.col.f32.tf32.tf32.f32 "
        "{%0,%1,%2,%3}, {%4,%5,%6,%7}, {%8,%9}, {%0,%1,%2,%3};"
        : "+f"(d[0]), "+f"(d[1]), "+f"(d[2]), "+f"(d[3])
        : "r"(a[0]), "r"(a[1]), "r"(a[2]), "r"(a[3]), "r"(b0), "r"(b1));
}

// ---------------- tiny kernels ----------------------------------------------
__global__ void zero_stats_kernel() {
    int i = threadIdx.x;
    if (i < C) {
        #pragma unroll
        for (int s = 0; s < 4; s++) { g_sum[s][i] = 0.f; g_sq[s][i] = 0.f; }
    }
}

__global__ void finalize_kernel(int s, const float* __restrict__ gamma,
                                const float* __restrict__ beta, float invN) {
    int c = threadIdx.x;
    float mean = g_sum[s][c] * invN;
    float var  = g_sq[s][c] * invN - mean * mean;
    float sc   = gamma[c] * rsqrtf(var + 1e-5f);
    g_scale[s][c] = sc;
    g_shift[s][c] = beta[c] - mean * sc;
}

// ---------------- tf32 tensor-core GEMM v3 -----------------------------------
// Block tile: 128 rows x 64 cols (grid.y selects column half).
// smem ~103 KB -> 2 blocks/SM: load phase of one block overlaps MMA of the other.
constexpr int PADA = 136;   // A row stride (uint32)
constexpr int PADB = 68;    // W row stride (uint32)
constexpr int BMR  = 128;   // rows per block

template <int MODE>
__global__ __launch_bounds__(256, 2)
void gemm_kernel(const float* __restrict__ A,
                 const float* __restrict__ W,
                 const float* __restrict__ bias,
                 float* __restrict__ out,
                 int stat_in, int stat_out, int N) {
    extern __shared__ float smem[];
    uint32_t* sW   = (uint32_t*)smem;          // [128][68] tf32 bits
    uint32_t* sA   = sW + 128 * PADB;          // [128][136] tf32 bits
    float*    sAf  = (float*)sA;               // reused for output staging
    float*    sSum = (float*)(sA + BMR * PADA);
    float*    sSq  = sSum + 64;

    const int tid  = threadIdx.x;
    const int row0 = blockIdx.x * BMR;
    const int ch0  = blockIdx.y * 64;

    if (tid < 64) { sSum[tid] = 0.f; sSq[tid] = 0.f; }

    // stage W half (tf32): k 0..127, n 0..63
    for (int i = tid * 4; i < 128 * 64; i += 1024) {
        int k = i >> 6, n = i & 63;
        float4 w = *(const float4*)(W + k * C + ch0 + n);
        uint4 t4;
        t4.x = f2tf32(w.x); t4.y = f2tf32(w.y);
        t4.z = f2tf32(w.z); t4.w = f2tf32(w.w);
        *(uint4*)(sW + k * PADB + n) = t4;
    }
    // stage A' (BN transform + tf32): full K
    for (int i = tid * 4; i < BMR * C; i += 1024) {
        int r = i >> 7, c = i & 127;
        int row = row0 + r;
        float4 v = make_float4(0.f, 0.f, 0.f, 0.f);
        if (row < N) v = *(const float4*)(A + (size_t)row * C + c);
        if (MODE >= 1) {
            v.x = fmaf(v.x, g_scale[stat_in][c + 0], g_shift[stat_in][c + 0]);
            v.y = fmaf(v.y, g_scale[stat_in][c + 1], g_shift[stat_in][c + 1]);
            v.z = fmaf(v.z, g_scale[stat_in][c + 2], g_shift[stat_in][c + 2]);
            v.w = fmaf(v.w, g_scale[stat_in][c + 3], g_shift[stat_in][c + 3]);
            if (MODE == 2) {
                v.x = fmaxf(v.x, 0.f); v.y = fmaxf(v.y, 0.f);
                v.z = fmaxf(v.z, 0.f); v.w = fmaxf(v.w, 0.f);
            }
        }
        uint4 t4;
        t4.x = f2tf32(v.x); t4.y = f2tf32(v.y);
        t4.z = f2tf32(v.z); t4.w = f2tf32(v.w);
        *(uint4*)(sA + r * PADA + c) = t4;
    }
    __syncthreads();

    const int warp = tid >> 5, lane = tid & 31;
    const int g = lane >> 2, t = lane & 3;
    const int r0w = warp * 16;

    float d[8][4];
    #pragma unroll
    for (int nf = 0; nf < 8; nf++)
        #pragma unroll
        for (int j = 0; j < 4; j++) d[nf][j] = 0.f;

    #pragma unroll 1
    for (int ks = 0; ks < 16; ks++) {
        const int k0 = ks * 8;
        uint32_t a[4];
        const uint32_t* p = sA + (r0w + g) * PADA + k0 + t;
        a[0] = p[0];
        a[1] = p[8 * PADA];
        a[2] = p[4];
        a[3] = p[8 * PADA + 4];
        const uint32_t* bp = sW + (k0 + t) * PADB + g;
        #pragma unroll
        for (int nf = 0; nf < 8; nf++) {
            uint32_t b0 = bp[nf * 8];
            uint32_t b1 = bp[4 * PADB + nf * 8];
            mma_tf32(d[nf], a, b0, b1);
        }
    }
    __syncthreads();

    // stage results into sAf [128 rows][64 cols] (stride PADA)
    #pragma unroll
    for (int nf = 0; nf < 8; nf++) {
        int row = r0w + g;
        int col = nf * 8 + 2 * t;
        *(float2*)(sAf + row * PADA + col)       = make_float2(d[nf][0], d[nf][1]);
        *(float2*)(sAf + (row + 8) * PADA + col) = make_float2(d[nf][2], d[nf][3]);
    }
    __syncthreads();

    // coalesced store + bias + stats
    const int c4 = (tid & 15) * 4;        // 0..60
    const int rr = tid >> 4;              // 0..15
    float4 bv = *(const float4*)(bias + ch0 + c4);
    float ls0 = 0.f, ls1 = 0.f, ls2 = 0.f, ls3 = 0.f;
    float lq0 = 0.f, lq1 = 0.f, lq2 = 0.f, lq3 = 0.f;
    #pragma unroll
    for (int it = 0; it < 8; it++) {
        int r = rr + it * 16;
        int row = row0 + r;
        if (row < N) {
            float4 v = *(float4*)(sAf + r * PADA + c4);
            v.x += bv.x; v.y += bv.y; v.z += bv.z; v.w += bv.w;
            *(float4*)(out + (size_t)row * C + ch0 + c4) = v;
            ls0 += v.x; ls1 += v.y; ls2 += v.z; ls3 += v.w;
            lq0 += v.x * v.x; lq1 += v.y * v.y;
            lq2 += v.z * v.z; lq3 += v.w * v.w;
        }
    }
    atomicAdd(&sSum[c4 + 0], ls0); atomicAdd(&sSum[c4 + 1], ls1);
    atomicAdd(&sSum[c4 + 2], ls2); atomicAdd(&sSum[c4 + 3], ls3);
    atomicAdd(&sSq[c4 + 0], lq0);  atomicAdd(&sSq[c4 + 1], lq1);
    atomicAdd(&sSq[c4 + 2], lq2);  atomicAdd(&sSq[c4 + 3], lq3);
    __syncthreads();
    if (tid < 64) {
        atomicAdd(&g_sum[stat_out][ch0 + tid], sSum[tid]);
        atomicAdd(&g_sq[stat_out][ch0 + tid],  sSq[tid]);
    }
}

// ---------------- gather + max-pool v5 (R6 verbatim: barrier-free, shfl) -----
__global__ __launch_bounds__(256)
void gather_kernel(const float* __restrict__ pe,
                   const int* __restrict__ knn,
                   float* __restrict__ pooled, int N) {
    const int w    = (blockIdx.x * blockDim.x + threadIdx.x) >> 5;
    const int lane = threadIdx.x & 31;
    const int kg   = lane >> 3;            // 0..3
    const int cg   = lane & 7;             // 0..7
    const int c4   = (w & 3) * 32 + cg * 4;
    const int nGroups = (gridDim.x * blockDim.x) >> 7;

    const float4 sc = *(const float4*)(&g_scale[0][c4]);
    const float4 sh = *(const float4*)(&g_shift[0][c4]);

    float4 lsum = make_float4(0.f, 0.f, 0.f, 0.f);
    float4 lsq  = make_float4(0.f, 0.f, 0.f, 0.f);

    for (int n = (w >> 2); n < N; n += nGroups) {
        int4 idx = __ldg((const int4*)(knn + (size_t)n * KN) + kg);
        const float4* peBase =
            (const float4*)(pe + (((size_t)n * KN + kg * 4) << 7) + c4);
        float4 pv0 = __ldcs(peBase);
        float4 pv1 = __ldcs(peBase + 32);
        float4 pv2 = __ldcs(peBase + 64);
        float4 pv3 = __ldcs(peBase + 96);
        float4 h0 = __ldg((const float4*)(g_h0 + (((size_t)idx.x) << 7) + c4));
        float4 h1 = __ldg((const float4*)(g_h0 + (((size_t)idx.y) << 7) + c4));
        float4 h2 = __ldg((const float4*)(g_h0 + (((size_t)idx.z) << 7) + c4));
        float4 h3 = __ldg((const float4*)(g_h0 + (((size_t)idx.w) << 7) + c4));

        float4 m = make_float4(-CUDART_INF_F, -CUDART_INF_F,
                               -CUDART_INF_F, -CUDART_INF_F);
        #define GMAX(pv, hv)                                              \
        {                                                                 \
            float4 h = hv;                                                \
            h.x = fmaxf(fmaf(h.x, sc.x, sh.x), 0.f);                      \
            h.y = fmaxf(fmaf(h.y, sc.y, sh.y), 0.f);                      \
            h.z = fmaxf(fmaf(h.z, sc.z, sh.z), 0.f);                      \
            h.w = fmaxf(fmaf(h.w, sc.w, sh.w), 0.f);                      \
            m.x = fmaxf(m.x, pv.x + h.x);                                 \
            m.y = fmaxf(m.y, pv.y + h.y);                                 \
            m.z = fmaxf(m.z, pv.z + h.z);                                 \
            m.w = fmaxf(m.w, pv.w + h.w);                                 \
        }
        GMAX(pv0, h0) GMAX(pv1, h1) GMAX(pv2, h2) GMAX(pv3, h3)
        #undef GMAX

        m.x = fmaxf(m.x, __shfl_xor_sync(0xffffffffu, m.x, 8));
        m.y = fmaxf(m.y, __shfl_xor_sync(0xffffffffu, m.y, 8));
        m.z = fmaxf(m.z, __shfl_xor_sync(0xffffffffu, m.z, 8));
        m.w = fmaxf(m.w, __shfl_xor_sync(0xffffffffu, m.w, 8));
        m.x = fmaxf(m.x, __shfl_xor_sync(0xffffffffu, m.x, 16));
        m.y = fmaxf(m.y, __shfl_xor_sync(0xffffffffu, m.y, 16));
        m.z = fmaxf(m.z, __shfl_xor_sync(0xffffffffu, m.z, 16));
        m.w = fmaxf(m.w, __shfl_xor_sync(0xffffffffu, m.w, 16));

        if (kg == 0) {
            *(float4*)(pooled + (((size_t)n) << 7) + c4) = m;
            lsum.x += m.x; lsum.y += m.y; lsum.z += m.z; lsum.w += m.w;
            lsq.x += m.x * m.x; lsq.y += m.y * m.y;
            lsq.z += m.z * m.z; lsq.w += m.w * m.w;
        }
    }

    if (kg == 0) {
        atomicAdd(&g_sum[1][c4 + 0], lsum.x); atomicAdd(&g_sum[1][c4 + 1], lsum.y);
        atomicAdd(&g_sum[1][c4 + 2], lsum.z); atomicAdd(&g_sum[1][c4 + 3], lsum.w);
        atomicAdd(&g_sq[1][c4 + 0], lsq.x);   atomicAdd(&g_sq[1][c4 + 1], lsq.y);
        atomicAdd(&g_sq[1][c4 + 2], lsq.z);   atomicAdd(&g_sq[1][c4 + 3], lsq.w);
    }
}

// ---------------- residual epilogue ------------------------------------------
__global__ void final_kernel(const float* __restrict__ f,
                             float* __restrict__ out, int N) {
    int i = (blockIdx.x * blockDim.x + threadIdx.x) * 4;
    if (i >= N * C) return;
    int c = i & (C - 1);
    float4 fv = *(const float4*)(f + i);
    float4 uv = *(const float4*)(g_u + i);
    float4 o;
    o.x = fmaxf(fv.x + fmaf(uv.x, g_scale[3][c + 0], g_shift[3][c + 0]), 0.f);
    o.y = fmaxf(fv.y + fmaf(uv.y, g_scale[3][c + 1], g_shift[3][c + 1]), 0.f);
    o.z = fmaxf(fv.z + fmaf(uv.z, g_scale[3][c + 2], g_shift[3][c + 2]), 0.f);
    o.w = fmaxf(fv.w + fmaf(uv.w, g_scale[3][c + 3], g_shift[3][c + 3]), 0.f);
    *(float4*)(out + i) = o;
}

// ---------------- launcher ----------------------------------------------------
extern "C" void kernel_launch(void* const* d_in, const int* in_sizes, int n_in,
                              void* d_out, int out_size) {
    const float* f_in  = (const float*)d_in[1];
    const float* pe    = (const float*)d_in[2];
    const int*   knn   = (const int*)  d_in[3];
    const float* W_pre = (const float*)d_in[4];
    const float* b_pre = (const float*)d_in[5];
    const float* g1    = (const float*)d_in[6];
    const float* be1   = (const float*)d_in[7];
    const float* g2    = (const float*)d_in[8];
    const float* be2   = (const float*)d_in[9];
    const float* W_f1  = (const float*)d_in[10];
    const float* b_f1  = (const float*)d_in[11];
    const float* g3    = (const float*)d_in[12];
    const float* be3   = (const float*)d_in[13];
    const float* W_f2  = (const float*)d_in[14];
    const float* b_f2  = (const float*)d_in[15];
    const float* g4    = (const float*)d_in[16];
    const float* be4   = (const float*)d_in[17];
    float* out = (float*)d_out;

    const int N = in_sizes[0] / 3;
    const float invN = 1.0f / (float)N;

    float *p_h0, *p_pooled, *p_t, *p_u;
    cudaGetSymbolAddress((void**)&p_h0, g_h0);
    cudaGetSymbolAddress((void**)&p_pooled, g_pooled);
    cudaGetSymbolAddress((void**)&p_t, g_t);
    cudaGetSymbolAddress((void**)&p_u, g_u);

    const int SMEM_GEMM = (128 * PADB + BMR * PADA + 2 * 64) * (int)sizeof(float);
    cudaFuncSetAttribute(gemm_kernel<0>, cudaFuncAttributeMaxDynamicSharedMemorySize, SMEM_GEMM);
    cudaFuncSetAttribute(gemm_kernel<1>, cudaFuncAttributeMaxDynamicSharedMemorySize, SMEM_GEMM);
    cudaFuncSetAttribute(gemm_kernel<2>, cudaFuncAttributeMaxDynamicSharedMemorySize, SMEM_GEMM);

    const dim3 gemmGrid((N + BMR - 1) / BMR, 2);
    const int gatherGrid = 1184;
    const int finalGrid  = (N * C / 4 + 255) / 256;

    zero_stats_kernel<<<1, 128>>>();

    gemm_kernel<0><<<gemmGrid, 256, SMEM_GEMM>>>(f_in, W_pre, b_pre, p_h0, 0, 0, N);
    finalize_kernel<<<1, C>>>(0, g1, be1, invN);

    gather_kernel<<<gatherGrid, 256>>>(pe, knn, p_pooled, N);
    finalize_kernel<<<1, C>>>(1, g2, be2, invN);

    gemm_kernel<1><<<gemmGrid, 256, SMEM_GEMM>>>(p_pooled, W_f1, b_f1, p_t, 1, 2, N);
    finalize_kernel<<<1, C>>>(2, g3, be3, invN);

    gemm_kernel<2><<<gemmGrid, 256, SMEM_GEMM>>>(p_t, W_f2, b_f2, p_u, 2, 3, N);
    finalize_kernel<<<1, C>>>(3, g4, be4, invN);

    final_kernel<<<finalGrid, 256>>>(f_in, out, N);
}

// round 11
// speedup vs baseline: 1.3062x; 1.3062x over previous
#include <cuda_runtime.h>
#include <cstdint>
#include <math_constants.h>

constexpr int C  = 128;
constexpr int KN = 16;
constexpr int NMAX = 100000;

// ---------------- device scratch -------------------------------------------
__device__ float g_h0[(size_t)NMAX * C];
__device__ float g_pooled[(size_t)NMAX * C];
__device__ float g_t[(size_t)NMAX * C];
__device__ float g_u[(size_t)NMAX * C];

__device__ float g_sum[4][C];
__device__ float g_sq[4][C];

// ---------------- helpers ----------------------------------------------------
__device__ __forceinline__ uint32_t f2tf32(float x) {
    uint32_t r;
    asm("cvt.rna.tf32.f32 %0, %1;" : "=r"(r) : "f"(x));
    return r;
}

__device__ __forceinline__ void mma_tf32(float* d, const uint32_t* a,
                                         uint32_t b0, uint32_t b1) {
    asm volatile(
        "mma.sync.aligned.m16n8k8.row.col.f32.tf32.tf32.f32 "
        "{%0,%1,%2,%3}, {%4,%5,%6,%7}, {%8,%9}, {%0,%1,%2,%3};"
        : "+f"(d[0]), "+f"(d[1]), "+f"(d[2]), "+f"(d[3])
        : "r"(a[0]), "r"(a[1]), "r"(a[2]), "r"(a[3]), "r"(b0), "r"(b1));
}

// per-channel BN coeff from accumulated stats (slot s), channel c
__device__ __forceinline__ void bn_coeff(int s, int c, const float* gamma,
                                         const float* beta, float invN,
                                         float& sc, float& sh) {
    float mean = g_sum[s][c] * invN;
    float var  = g_sq[s][c] * invN - mean * mean;
    sc = __ldg(gamma + c) * rsqrtf(var + 1e-5f);
    sh = __ldg(beta + c) - mean * sc;
}

// ---------------- tiny kernels ----------------------------------------------
__global__ void zero_stats_kernel() {
    int i = threadIdx.x;
    if (i < C) {
        #pragma unroll
        for (int s = 0; s < 4; s++) { g_sum[s][i] = 0.f; g_sq[s][i] = 0.f; }
    }
}

// ---------------- tf32 tensor-core GEMM (R6 core + inline BN finalize) -------
constexpr int PADW = 136;
constexpr int BM   = 256;

template <int MODE>
__global__ __launch_bounds__(256, 1)
void gemm_kernel(const float* __restrict__ A,
                 const float* __restrict__ W,
                 const float* __restrict__ bias,
                 float* __restrict__ out,
                 const float* __restrict__ gamma,
                 const float* __restrict__ beta,
                 float invN,
                 int stat_in, int stat_out, int N) {
    extern __shared__ float smem[];
    uint32_t* sW  = (uint32_t*)smem;            // [128][136] tf32 bits
    uint32_t* sA  = sW + 128 * PADW;            // [256][136] tf32 bits
    float*    sAf = (float*)sA;                 // reused for output staging
    float*    sSum   = (float*)(sA + BM * PADW);
    float*    sSq    = sSum + C;
    float*    sScale = sSq + C;
    float*    sShift = sScale + C;

    const int tid  = threadIdx.x;
    const int row0 = blockIdx.x * BM;

    if (tid < C) {
        sSum[tid] = 0.f; sSq[tid] = 0.f;
        if (MODE >= 1) {
            float sc, sh;
            bn_coeff(stat_in, tid, gamma, beta, invN, sc, sh);
            sScale[tid] = sc; sShift[tid] = sh;
        }
    }
    if (MODE >= 1) __syncthreads();

    for (int i = tid * 4; i < C * C; i += 1024) {
        int k = i >> 7, n = i & 127;
        float4 w = *(const float4*)(W + i);
        uint4 t4;
        t4.x = f2tf32(w.x); t4.y = f2tf32(w.y);
        t4.z = f2tf32(w.z); t4.w = f2tf32(w.w);
        *(uint4*)(sW + k * PADW + n) = t4;
    }
    for (int i = tid * 4; i < BM * C; i += 1024) {
        int r = i >> 7, c = i & 127;
        int row = row0 + r;
        float4 v = make_float4(0.f, 0.f, 0.f, 0.f);
        if (row < N) v = *(const float4*)(A + (size_t)row * C + c);
        if (MODE >= 1) {
            v.x = fmaf(v.x, sScale[c + 0], sShift[c + 0]);
            v.y = fmaf(v.y, sScale[c + 1], sShift[c + 1]);
            v.z = fmaf(v.z, sScale[c + 2], sShift[c + 2]);
            v.w = fmaf(v.w, sScale[c + 3], sShift[c + 3]);
            if (MODE == 2) {
                v.x = fmaxf(v.x, 0.f); v.y = fmaxf(v.y, 0.f);
                v.z = fmaxf(v.z, 0.f); v.w = fmaxf(v.w, 0.f);
            }
        }
        uint4 t4;
        t4.x = f2tf32(v.x); t4.y = f2tf32(v.y);
        t4.z = f2tf32(v.z); t4.w = f2tf32(v.w);
        *(uint4*)(sA + r * PADW + c) = t4;
    }
    __syncthreads();

    const int warp = tid >> 5, lane = tid & 31;
    const int g = lane >> 2, t = lane & 3;
    const int r0w = warp * 32;

    float d[2][16][4];
    #pragma unroll
    for (int rs = 0; rs < 2; rs++)
        #pragma unroll
        for (int nf = 0; nf < 16; nf++)
            #pragma unroll
            for (int j = 0; j < 4; j++) d[rs][nf][j] = 0.f;

    #pragma unroll 1
    for (int ks = 0; ks < 16; ks++) {
        const int k0 = ks * 8;
        uint32_t a[2][4];
        #pragma unroll
        for (int rs = 0; rs < 2; rs++) {
            const uint32_t* p = sA + (r0w + rs * 16 + g) * PADW + k0 + t;
            a[rs][0] = p[0];
            a[rs][1] = p[8 * PADW];
            a[rs][2] = p[4];
            a[rs][3] = p[8 * PADW + 4];
        }
        const uint32_t* bp = sW + (k0 + t) * PADW + g;
        #pragma unroll
        for (int nf = 0; nf < 16; nf++) {
            uint32_t b0 = bp[nf * 8];
            uint32_t b1 = bp[4 * PADW + nf * 8];
            mma_tf32(d[0][nf], a[0], b0, b1);
            mma_tf32(d[1][nf], a[1], b0, b1);
        }
    }
    __syncthreads();

    #pragma unroll
    for (int rs = 0; rs < 2; rs++) {
        #pragma unroll
        for (int nf = 0; nf < 16; nf++) {
            int row = r0w + rs * 16 + g;
            int col = nf * 8 + 2 * t;
            *(float2*)(sAf + row * PADW + col) =
                make_float2(d[rs][nf][0], d[rs][nf][1]);
            *(float2*)(sAf + (row + 8) * PADW + col) =
                make_float2(d[rs][nf][2], d[rs][nf][3]);
        }
    }
    __syncthreads();

    const int c4 = (tid * 4) & 127;
    float4 bv = *(const float4*)(bias + c4);
    float ls0 = 0.f, ls1 = 0.f, ls2 = 0.f, ls3 = 0.f;
    float lq0 = 0.f, lq1 = 0.f, lq2 = 0.f, lq3 = 0.f;
    #pragma unroll 1
    for (int it = 0; it < 32; it++) {
        int r = (tid >> 5) + it * 8;
        int row = row0 + r;
        if (row < N) {
            float4 v = *(float4*)(sAf + r * PADW + c4);
            v.x += bv.x; v.y += bv.y; v.z += bv.z; v.w += bv.w;
            *(float4*)(out + (size_t)row * C + c4) = v;
            ls0 += v.x; ls1 += v.y; ls2 += v.z; ls3 += v.w;
            lq0 += v.x * v.x; lq1 += v.y * v.y;
            lq2 += v.z * v.z; lq3 += v.w * v.w;
        }
    }
    atomicAdd(&sSum[c4 + 0], ls0); atomicAdd(&sSum[c4 + 1], ls1);
    atomicAdd(&sSum[c4 + 2], ls2); atomicAdd(&sSum[c4 + 3], ls3);
    atomicAdd(&sSq[c4 + 0], lq0);  atomicAdd(&sSq[c4 + 1], lq1);
    atomicAdd(&sSq[c4 + 2], lq2);  atomicAdd(&sSq[c4 + 3], lq3);
    __syncthreads();
    if (tid < C) {
        atomicAdd(&g_sum[stat_out][tid], sSum[tid]);
        atomicAdd(&g_sq[stat_out][tid],  sSq[tid]);
    }
}

// ---------------- gather + max-pool v7 (2-point ILP, inline bn1) -------------
__global__ __launch_bounds__(256)
void gather_kernel(const float* __restrict__ pe,
                   const int* __restrict__ knn,
                   float* __restrict__ pooled,
                   const float* __restrict__ gamma,
                   const float* __restrict__ beta,
                   float invN, int N) {
    const int w    = (blockIdx.x * blockDim.x + threadIdx.x) >> 5;
    const int lane = threadIdx.x & 31;
    const int kg   = lane >> 3;            // 0..3
    const int cg   = lane & 7;             // 0..7
    const int c4   = (w & 3) * 32 + cg * 4;
    const int nG   = (gridDim.x * blockDim.x) >> 7;

    float4 sc, sh;
    bn_coeff(0, c4 + 0, gamma, beta, invN, sc.x, sh.x);
    bn_coeff(0, c4 + 1, gamma, beta, invN, sc.y, sh.y);
    bn_coeff(0, c4 + 2, gamma, beta, invN, sc.z, sh.z);
    bn_coeff(0, c4 + 3, gamma, beta, invN, sc.w, sh.w);

    float4 lsum = make_float4(0.f, 0.f, 0.f, 0.f);
    float4 lsq  = make_float4(0.f, 0.f, 0.f, 0.f);

    for (int n = (w >> 2); n < N; n += 2 * nG) {
        const int  n2 = n + nG;
        const bool v2 = (n2 < N);
        const int  n2c = v2 ? n2 : n;     // clamp: uniform loads, result ignored

        int4 iA = __ldg((const int4*)(knn + (size_t)n  * KN) + kg);
        int4 iB = __ldg((const int4*)(knn + (size_t)n2c * KN) + kg);

        const float4* peA =
            (const float4*)(pe + (((size_t)n * KN + kg * 4) << 7) + c4);
        const float4* peB =
            (const float4*)(pe + (((size_t)n2c * KN + kg * 4) << 7) + c4);

        float4 pa0 = __ldcs(peA),      pa1 = __ldcs(peA + 32);
        float4 pa2 = __ldcs(peA + 64), pa3 = __ldcs(peA + 96);
        float4 pb0 = __ldcs(peB),      pb1 = __ldcs(peB + 32);
        float4 pb2 = __ldcs(peB + 64), pb3 = __ldcs(peB + 96);

        float4 ha0 = __ldg((const float4*)(g_h0 + (((size_t)iA.x) << 7) + c4));
        float4 ha1 = __ldg((const float4*)(g_h0 + (((size_t)iA.y) << 7) + c4));
        float4 ha2 = __ldg((const float4*)(g_h0 + (((size_t)iA.z) << 7) + c4));
        float4 ha3 = __ldg((const float4*)(g_h0 + (((size_t)iA.w) << 7) + c4));
        float4 hb0 = __ldg((const float4*)(g_h0 + (((size_t)iB.x) << 7) + c4));
        float4 hb1 = __ldg((const float4*)(g_h0 + (((size_t)iB.y) << 7) + c4));
        float4 hb2 = __ldg((const float4*)(g_h0 + (((size_t)iB.z) << 7) + c4));
        float4 hb3 = __ldg((const float4*)(g_h0 + (((size_t)iB.w) << 7) + c4));

        float4 mA = make_float4(-CUDART_INF_F, -CUDART_INF_F,
                                -CUDART_INF_F, -CUDART_INF_F);
        float4 mB = mA;

        #define GMAX(m, pv, hv)                                           \
        {                                                                 \
            float4 h = hv;                                                \
            h.x = fmaxf(fmaf(h.x, sc.x, sh.x), 0.f);                      \
            h.y = fmaxf(fmaf(h.y, sc.y, sh.y), 0.f);                      \
            h.z = fmaxf(fmaf(h.z, sc.z, sh.z), 0.f);                      \
            h.w = fmaxf(fmaf(h.w, sc.w, sh.w), 0.f);                      \
            m.x = fmaxf(m.x, pv.x + h.x);                                 \
            m.y = fmaxf(m.y, pv.y + h.y);                                 \
            m.z = fmaxf(m.z, pv.z + h.z);                                 \
            m.w = fmaxf(m.w, pv.w + h.w);                                 \
        }
        GMAX(mA, pa0, ha0) GMAX(mA, pa1, ha1)
        GMAX(mA, pa2, ha2) GMAX(mA, pa3, ha3)
        GMAX(mB, pb0, hb0) GMAX(mB, pb1, hb1)
        GMAX(mB, pb2, hb2) GMAX(mB, pb3, hb3)
        #undef GMAX

        #define WRED(m)                                                    \
        m.x = fmaxf(m.x, __shfl_xor_sync(0xffffffffu, m.x, 8));            \
        m.y = fmaxf(m.y, __shfl_xor_sync(0xffffffffu, m.y, 8));            \
        m.z = fmaxf(m.z, __shfl_xor_sync(0xffffffffu, m.z, 8));            \
        m.w = fmaxf(m.w, __shfl_xor_sync(0xffffffffu, m.w, 8));            \
        m.x = fmaxf(m.x, __shfl_xor_sync(0xffffffffu, m.x, 16));           \
        m.y = fmaxf(m.y, __shfl_xor_sync(0xffffffffu, m.y, 16));           \
        m.z = fmaxf(m.z, __shfl_xor_sync(0xffffffffu, m.z, 16));           \
        m.w = fmaxf(m.w, __shfl_xor_sync(0xffffffffu, m.w, 16));
        WRED(mA)
        WRED(mB)
        #undef WRED

        if (kg == 0) {
            *(float4*)(pooled + (((size_t)n) << 7) + c4) = mA;
            lsum.x += mA.x; lsum.y += mA.y; lsum.z += mA.z; lsum.w += mA.w;
            lsq.x += mA.x * mA.x; lsq.y += mA.y * mA.y;
            lsq.z += mA.z * mA.z; lsq.w += mA.w * mA.w;
            if (v2) {
                *(float4*)(pooled + (((size_t)n2) << 7) + c4) = mB;
                lsum.x += mB.x; lsum.y += mB.y; lsum.z += mB.z; lsum.w += mB.w;
                lsq.x += mB.x * mB.x; lsq.y += mB.y * mB.y;
                lsq.z += mB.z * mB.z; lsq.w += mB.w * mB.w;
            }
        }
    }

    if (kg == 0) {
        atomicAdd(&g_sum[1][c4 + 0], lsum.x); atomicAdd(&g_sum[1][c4 + 1], lsum.y);
        atomicAdd(&g_sum[1][c4 + 2], lsum.z); atomicAdd(&g_sum[1][c4 + 3], lsum.w);
        atomicAdd(&g_sq[1][c4 + 0], lsq.x);   atomicAdd(&g_sq[1][c4 + 1], lsq.y);
        atomicAdd(&g_sq[1][c4 + 2], lsq.z);   atomicAdd(&g_sq[1][c4 + 3], lsq.w);
    }
}

// ---------------- residual epilogue (inline bn4) ------------------------------
__global__ void final_kernel(const float* __restrict__ f,
                             float* __restrict__ out,
                             const float* __restrict__ gamma,
                             const float* __restrict__ beta,
                             float invN, int N) {
    int i = (blockIdx.x * blockDim.x + threadIdx.x) * 4;
    if (i >= N * C) return;
    int c = i & (C - 1);
    float4 sc, sh;
    bn_coeff(3, c + 0, gamma, beta, invN, sc.x, sh.x);
    bn_coeff(3, c + 1, gamma, beta, invN, sc.y, sh.y);
    bn_coeff(3, c + 2, gamma, beta, invN, sc.z, sh.z);
    bn_coeff(3, c + 3, gamma, beta, invN, sc.w, sh.w);
    float4 fv = *(const float4*)(f + i);
    float4 uv = *(const float4*)(g_u + i);
    float4 o;
    o.x = fmaxf(fv.x + fmaf(uv.x, sc.x, sh.x), 0.f);
    o.y = fmaxf(fv.y + fmaf(uv.y, sc.y, sh.y), 0.f);
    o.z = fmaxf(fv.z + fmaf(uv.z, sc.z, sh.z), 0.f);
    o.w = fmaxf(fv.w + fmaf(uv.w, sc.w, sh.w), 0.f);
    *(float4*)(out + i) = o;
}

// ---------------- launcher ----------------------------------------------------
extern "C" void kernel_launch(void* const* d_in, const int* in_sizes, int n_in,
                              void* d_out, int out_size) {
    const float* f_in  = (const float*)d_in[1];
    const float* pe    = (const float*)d_in[2];
    const int*   knn   = (const int*)  d_in[3];
    const float* W_pre = (const float*)d_in[4];
    const float* b_pre = (const float*)d_in[5];
    const float* g1    = (const float*)d_in[6];
    const float* be1   = (const float*)d_in[7];
    const float* g2    = (const float*)d_in[8];
    const float* be2   = (const float*)d_in[9];
    const float* W_f1  = (const float*)d_in[10];
    const float* b_f1  = (const float*)d_in[11];
    const float* g3    = (const float*)d_in[12];
    const float* be3   = (const float*)d_in[13];
    const float* W_f2  = (const float*)d_in[14];
    const float* b_f2  = (const float*)d_in[15];
    const float* g4    = (const float*)d_in[16];
    const float* be4   = (const float*)d_in[17];
    float* out = (float*)d_out;

    const int N = in_sizes[0] / 3;
    const float invN = 1.0f / (float)N;

    float *p_h0, *p_pooled, *p_t, *p_u;
    cudaGetSymbolAddress((void**)&p_h0, g_h0);
    cudaGetSymbolAddress((void**)&p_pooled, g_pooled);
    cudaGetSymbolAddress((void**)&p_t, g_t);
    cudaGetSymbolAddress((void**)&p_u, g_u);

    const int SMEM_GEMM = (128 * PADW + BM * PADW + 4 * C) * (int)sizeof(float);
    cudaFuncSetAttribute(gemm_kernel<0>, cudaFuncAttributeMaxDynamicSharedMemorySize, SMEM_GEMM);
    cudaFuncSetAttribute(gemm_kernel<1>, cudaFuncAttributeMaxDynamicSharedMemorySize, SMEM_GEMM);
    cudaFuncSetAttribute(gemm_kernel<2>, cudaFuncAttributeMaxDynamicSharedMemorySize, SMEM_GEMM);

    const int gemmGrid   = (N + BM - 1) / BM;
    const int gatherGrid = 1184;
    const int finalGrid  = (N * C / 4 + 255) / 256;

    zero_stats_kernel<<<1, 128>>>();

    // h0 = f @ W_pre + b_pre, stats -> slot 0
    gemm_kernel<0><<<gemmGrid, 256, SMEM_GEMM>>>(
        f_in, W_pre, b_pre, p_h0, nullptr, nullptr, invN, 0, 0, N);

    // pooled = max_k(pe + relu(bn1(h0[knn]))), stats -> slot 1
    gather_kernel<<<gatherGrid, 256>>>(pe, knn, p_pooled, g1, be1, invN, N);

    // t = bn2(pooled) @ W_f1 + b_f1, stats -> slot 2
    gemm_kernel<1><<<gemmGrid, 256, SMEM_GEMM>>>(
        p_pooled, W_f1, b_f1, p_t, g2, be2, invN, 1, 2, N);

    // u = relu(bn3(t)) @ W_f2 + b_f2, stats -> slot 3
    gemm_kernel<2><<<gemmGrid, 256, SMEM_GEMM>>>(
        p_t, W_f2, b_f2, p_u, g3, be3, invN, 2, 3, N);

    // out = relu(f + bn4(u))
    final_kernel<<<finalGrid, 256>>>(f_in, out, g4, be4, invN, N);
}